// round 9
// baseline (speedup 1.0000x reference)
#include <cuda_runtime.h>
#include <cstdint>

#define N_USERS 100000
#define N_ITEMS 50000
#define N_NODES 150000
#define N_REL   5
#define NNZ     2000000
#define TOTE    (N_REL * NNZ)
#define D       64
#define B_EVAL  16384
#define NROWS   (2 * B_EVAL)
#define MAXCID  32768
#define CAP     64
#define OVF_CAP 8192
#define NBITW   ((N_NODES + 31) / 32)

typedef unsigned long long u64;

// ---------------- device scratch (no allocations allowed) -------------------
__device__ int      g_table[N_NODES];                  // -1 unused / -2 marked / cid
__device__ unsigned g_bits[NBITW];                     // 18.75KB: L1-resident mask
__device__ int      g_cnt;
__device__ int      g_counts[MAXCID * N_REL];
__device__ float2   g_pairs[(size_t)MAXCID * N_REL * CAP];
__device__ float    g_agg[(size_t)MAXCID * N_REL * D];
__device__ float    g_logits[(size_t)NROWS * D];
__device__ int      g_ovf_cnt;
__device__ int4     g_ovf[OVF_CAP];

// ---------------- helpers ---------------------------------------------------
__device__ __forceinline__ u64 pack2(float lo, float hi) {
    u64 r; asm("mov.b64 %0, {%1, %2};" : "=l"(r) : "f"(lo), "f"(hi)); return r;
}
__device__ __forceinline__ void unpack2(u64 v, float& lo, float& hi) {
    asm("mov.b64 {%0, %1}, %2;" : "=f"(lo), "=f"(hi) : "l"(v));
}
__device__ __forceinline__ void fma2(u64& d, u64 a, u64 b) {
    asm("fma.rn.f32x2 %0, %1, %2, %0;" : "+l"(d) : "l"(a), "l"(b));
}

// ---------------- K0: clear table / bits / counters -------------------------
__global__ void clear_kernel() {
    int i = blockIdx.x * blockDim.x + threadIdx.x;
    if (i < N_NODES) g_table[i] = -1;
    if (i < NBITW) g_bits[i] = 0u;
    if (i < MAXCID * N_REL) g_counts[i] = 0;
    if (i == 0) { g_cnt = 0; g_ovf_cnt = 0; }
}

// ---------------- K1a: mark needed nodes ------------------------------------
__global__ void mark_kernel(const int* __restrict__ users, const int* __restrict__ items) {
    int r = blockIdx.x * blockDim.x + threadIdx.x;
    if (r >= NROWS) return;
    int node = (r < B_EVAL) ? users[r] : (N_USERS + items[r - B_EVAL]);
    g_table[node] = -2;               // idempotent
    atomicOr(&g_bits[node >> 5], 1u << (node & 31));
}

// ---------------- K1b: assign compact ids -----------------------------------
__global__ void assign_kernel() {
    int i = blockIdx.x * blockDim.x + threadIdx.x;
    if (i >= N_NODES) return;
    if (g_table[i] == -2) g_table[i] = atomicAdd(&g_cnt, 1);
}

// ---------------- K2: bin surviving edges (bitmask prefilter) ---------------
__global__ void __launch_bounds__(256) bin_kernel(
    const int* __restrict__ rows, const int* __restrict__ cols,
    const float* __restrict__ vals)
{
    int i = blockIdx.x * blockDim.x + threadIdx.x;     // pack index
    if (i >= TOTE / 4) return;
    int e0 = i * 4;
    int k  = e0 / NNZ;                                 // pack-uniform (NNZ%4==0)

    int4 r4 = reinterpret_cast<const int4*>(rows)[i];

    // 4 independent L1-resident bit tests
    unsigned w0 = g_bits[r4.x >> 5];
    unsigned w1 = g_bits[r4.y >> 5];
    unsigned w2 = g_bits[r4.z >> 5];
    unsigned w3 = g_bits[r4.w >> 5];
    bool h[4];
    h[0] = (w0 >> (r4.x & 31)) & 1u;
    h[1] = (w1 >> (r4.y & 31)) & 1u;
    h[2] = (w2 >> (r4.z & 31)) & 1u;
    h[3] = (w3 >> (r4.w & 31)) & 1u;

    if (!(h[0] | h[1] | h[2] | h[3])) return;

    int4   c4 = reinterpret_cast<const int4*>(cols)[i];
    float4 v4 = reinterpret_cast<const float4*>(vals)[i];

    int r[4]   = {r4.x, r4.y, r4.z, r4.w};
    int c[4]   = {c4.x, c4.y, c4.z, c4.w};
    float v[4] = {v4.x, v4.y, v4.z, v4.w};

    // independent table lookups for survivors only
    int cid[4];
#pragma unroll
    for (int j = 0; j < 4; j++) cid[j] = h[j] ? g_table[r[j]] : -1;

#pragma unroll
    for (int j = 0; j < 4; j++) {
        if (h[j]) {
            int b = cid[j] * N_REL + k;
            int pos = atomicAdd(&g_counts[b], 1);
            if (pos < CAP) {
                g_pairs[(size_t)b * CAP + pos] = make_float2(__int_as_float(c[j]), v[j]);
            } else {
                int oi = atomicAdd(&g_ovf_cnt, 1);
                if (oi < OVF_CAP) g_ovf[oi] = make_int4(cid[j], k, c[j], __float_as_int(v[j]));
            }
        }
    }
}

// ---------------- K3: warp-per-bucket gather (padded 8-wide, MLP=8) ---------
__global__ void __launch_bounds__(256) gather_kernel(
    const float* __restrict__ uemb, const float* __restrict__ iemb)
{
    int gw   = (blockIdx.x * blockDim.x + threadIdx.x) >> 5;
    int lane = threadIdx.x & 31;
    if (gw >= MAXCID * N_REL) return;
    int cnt = g_counts[gw];
    if (cnt > CAP) cnt = CAP;
    float2 acc = make_float2(0.f, 0.f);
    const float2* pairs = &g_pairs[(size_t)gw * CAP];
    for (int base = 0; base < cnt; base += 32) {
        // lanes beyond cnt carry (c=0, v=0): pad edges read row 0 (L1 hit) * 0
        float2 p = make_float2(0.f, 0.f);
        if (base + lane < cnt) p = pairs[base + lane];
        int   c_l = __float_as_int(p.x);
        float v_l = p.y;
        int lim = cnt - base; if (lim > 32) lim = 32;
        int lim8 = (lim + 7) & ~7;                      // uniform, no remainder
        for (int t = 0; t < lim8; t += 8) {
            int   cc[8];
            float vv[8];
#pragma unroll
            for (int q = 0; q < 8; q++) {
                cc[q] = __shfl_sync(0xFFFFFFFFu, c_l, t + q);
                vv[q] = __shfl_sync(0xFFFFFFFFu, v_l, t + q);
            }
            float2 x[8];
#pragma unroll
            for (int q = 0; q < 8; q++) {
                const float2* er = (cc[q] < N_USERS)
                    ? reinterpret_cast<const float2*>(uemb + (size_t)cc[q] * D)
                    : reinterpret_cast<const float2*>(iemb + (size_t)(cc[q] - N_USERS) * D);
                x[q] = er[lane];
            }
#pragma unroll
            for (int q = 0; q < 8; q++) {
                acc.x += vv[q] * x[q].x;
                acc.y += vv[q] * x[q].y;
            }
        }
    }
    reinterpret_cast<float2*>(g_agg + (size_t)gw * D)[lane] = acc;
}

// ---------------- K3b: overflow fallback (expected empty) -------------------
__global__ void ovf_kernel(const float* __restrict__ uemb, const float* __restrict__ iemb) {
    int i = blockIdx.x * blockDim.x + threadIdx.x;
    int n = g_ovf_cnt; if (n > OVF_CAP) n = OVF_CAP;
    if (i >= n) return;
    int4 e = g_ovf[i];
    int cid = e.x, k = e.y, c = e.z;
    float v = __int_as_float(e.w);
    const float* Erow = (c < N_USERS) ? (uemb + (size_t)c * D)
                                      : (iemb + (size_t)(c - N_USERS) * D);
    float* dst = g_agg + ((size_t)cid * N_REL + k) * D;
    for (int m = 0; m < 16; m++) {
        float4 x = reinterpret_cast<const float4*>(Erow)[m];
        asm volatile("red.global.add.v4.f32 [%0], {%1, %2, %3, %4};"
                     :: "l"(dst + m * 4), "f"(x.x * v), "f"(x.y * v),
                        "f"(x.z * v), "f"(x.w * v) : "memory");
    }
}

// ---------------- K4: fused dense chain (512 thr, 4x4 tiles, f32x2) ---------
__global__ void __launch_bounds__(512) gemm_kernel(
    const int* __restrict__ users, const int* __restrict__ items,
    const float* __restrict__ W_rel, const float* __restrict__ b_rel,
    const float* __restrict__ affine_W, const float* __restrict__ affine_b)
{
    __shared__ float sX[128 * 64];   // X tile, then Y tile
    __shared__ float sW[64 * 64];    // W_k, then A_k

    int t  = threadIdx.x;
    int tx = t & 15;        // col group: 4 cols
    int ty = t >> 4;        // row group: 4 rows (0..31)
    int rowBase = blockIdx.x * 128;

    u64 acc2[4][2];
#pragma unroll
    for (int i = 0; i < 4; i++) { acc2[i][0] = 0ull; acc2[i][1] = 0ull; }

    for (int k = 0; k < N_REL; k++) {
        __syncthreads();
        // load X tile: 4 threads per row, 4 float4 each
        {
            int r = t >> 2, q = t & 3;
            int brow = rowBase + r;
            int node = (brow < B_EVAL) ? users[brow] : (N_USERS + items[brow - B_EVAL]);
            int cid = g_table[node];
            const float4* src = reinterpret_cast<const float4*>(
                g_agg + ((size_t)cid * N_REL + k) * D) + q * 4;
            float4* dst = reinterpret_cast<float4*>(&sX[r * 64]) + q * 4;
#pragma unroll
            for (int m = 0; m < 4; m++) dst[m] = src[m];
        }
        // load W_k (1024 float4 / 512 threads)
        {
            const float4* src = reinterpret_cast<const float4*>(W_rel + (size_t)k * 64 * 64);
            float4* dst = reinterpret_cast<float4*>(sW);
            dst[t] = src[t];
            dst[t + 512] = src[t + 512];
        }
        __syncthreads();

        // GEMM1: acc1 = bias; acc1 += X @ W   (f32x2 packed)
        u64 acc1[4][2];
        {
            const u64* bp = reinterpret_cast<const u64*>(b_rel + (size_t)k * 64 + tx * 4);
            u64 b01 = bp[0], b23 = bp[1];
#pragma unroll
            for (int i = 0; i < 4; i++) { acc1[i][0] = b01; acc1[i][1] = b23; }
        }
        for (int kk = 0; kk < 64; kk++) {
            longlong2 bq = *reinterpret_cast<const longlong2*>(&sW[kk * 64 + tx * 4]);
            u64 b0 = (u64)bq.x, b1 = (u64)bq.y;
#pragma unroll
            for (int i = 0; i < 4; i++) {
                float a = sX[(ty * 4 + i) * 64 + kk];
                u64 a2 = pack2(a, a);
                fma2(acc1[i][0], a2, b0);
                fma2(acc1[i][1], a2, b1);
            }
        }
        __syncthreads();   // done reading sX / sW

        // leaky + write Y into sX; load A_k into sW
#pragma unroll
        for (int i = 0; i < 4; i++) {
            float y0, y1, y2, y3;
            unpack2(acc1[i][0], y0, y1);
            unpack2(acc1[i][1], y2, y3);
            y0 = (y0 > 0.f) ? y0 : 0.2f * y0;
            y1 = (y1 > 0.f) ? y1 : 0.2f * y1;
            y2 = (y2 > 0.f) ? y2 : 0.2f * y2;
            y3 = (y3 > 0.f) ? y3 : 0.2f * y3;
            *reinterpret_cast<float4*>(&sX[(ty * 4 + i) * 64 + tx * 4]) =
                make_float4(y0, y1, y2, y3);
        }
        {
            const float4* src = reinterpret_cast<const float4*>(affine_W + (size_t)k * 64 * 64);
            float4* dst = reinterpret_cast<float4*>(sW);
            dst[t] = src[t];
            dst[t + 512] = src[t + 512];
        }
        __syncthreads();

        // GEMM2: acc2 += Y @ A_k   (f32x2 packed)
        for (int kk = 0; kk < 64; kk++) {
            longlong2 bq = *reinterpret_cast<const longlong2*>(&sW[kk * 64 + tx * 4]);
            u64 b0 = (u64)bq.x, b1 = (u64)bq.y;
#pragma unroll
            for (int i = 0; i < 4; i++) {
                float a = sX[(ty * 4 + i) * 64 + kk];
                u64 a2 = pack2(a, a);
                fma2(acc2[i][0], a2, b0);
                fma2(acc2[i][1], a2, b1);
            }
        }
    }

    // epilogue: + affine_b, store logits
    float ab0 = affine_b[tx * 4 + 0], ab1 = affine_b[tx * 4 + 1];
    float ab2 = affine_b[tx * 4 + 2], ab3 = affine_b[tx * 4 + 3];
#pragma unroll
    for (int i = 0; i < 4; i++) {
        float v0, v1, v2, v3;
        unpack2(acc2[i][0], v0, v1);
        unpack2(acc2[i][1], v2, v3);
        int row = rowBase + ty * 4 + i;
        *reinterpret_cast<float4*>(&g_logits[(size_t)row * D + tx * 4]) =
            make_float4(v0 + ab0, v1 + ab1, v2 + ab2, v3 + ab3);
    }
}

// ---------------- K5: out[b] = dot(logits[b], logits[B+b]) ------------------
__global__ void dot_kernel(float* __restrict__ out) {
    int b = blockIdx.x * blockDim.x + threadIdx.x;
    if (b >= B_EVAL) return;
    const float4* u = reinterpret_cast<const float4*>(g_logits + (size_t)b * D);
    const float4* v = reinterpret_cast<const float4*>(g_logits + (size_t)(B_EVAL + b) * D);
    float s = 0.f;
#pragma unroll
    for (int m = 0; m < 16; m++) {
        float4 a = u[m], c = v[m];
        s += a.x * c.x + a.y * c.y + a.z * c.z + a.w * c.w;
    }
    out[b] = s;
}

// ---------------------------------------------------------------------------
extern "C" void kernel_launch(void* const* d_in, const int* in_sizes, int n_in,
                              void* d_out, int out_size) {
    const int*   users    = (const int*)  d_in[0];
    const int*   items    = (const int*)  d_in[1];
    const int*   rows     = (const int*)  d_in[2];
    const int*   cols     = (const int*)  d_in[3];
    const float* vals     = (const float*)d_in[4];
    const float* uemb     = (const float*)d_in[5];
    const float* iemb     = (const float*)d_in[6];
    const float* W_rel    = (const float*)d_in[7];
    const float* b_rel    = (const float*)d_in[8];
    const float* affine_W = (const float*)d_in[9];
    const float* affine_b = (const float*)d_in[10];
    float* out = (float*)d_out;

    clear_kernel<<<(MAXCID * N_REL + 255) / 256, 256>>>();
    mark_kernel<<<(NROWS + 255) / 256, 256>>>(users, items);
    assign_kernel<<<(N_NODES + 255) / 256, 256>>>();
    bin_kernel<<<(TOTE / 4 + 255) / 256, 256>>>(rows, cols, vals);
    gather_kernel<<<(MAXCID * N_REL) / 8, 256>>>(uemb, iemb);
    ovf_kernel<<<OVF_CAP / 256, 256>>>(uemb, iemb);
    gemm_kernel<<<NROWS / 128, 512>>>(users, items, W_rel, b_rel, affine_W, affine_b);
    dot_kernel<<<(B_EVAL + 255) / 256, 256>>>(out);
}

// round 10
// speedup vs baseline: 1.0224x; 1.0224x over previous
#include <cuda_runtime.h>
#include <cstdint>

#define N_USERS 100000
#define N_ITEMS 50000
#define N_NODES 150000
#define N_REL   5
#define NNZ     2000000
#define TOTE    (N_REL * NNZ)
#define D       64
#define B_EVAL  16384
#define NROWS   (2 * B_EVAL)
#define MAXCID  32768
#define CAP     64
#define OVF_CAP 8192
#define NBITW   ((N_NODES + 31) / 32)

typedef unsigned long long u64;

// ---------------- device scratch (no allocations allowed) -------------------
__device__ int      g_table[N_NODES];                  // -1 unused / -2 marked / cid
__device__ unsigned g_bits[NBITW];                     // 18.75KB: L1-resident mask
__device__ int      g_cnt;
__device__ int      g_counts[MAXCID * N_REL];
__device__ float2   g_pairs[(size_t)MAXCID * N_REL * CAP];
__device__ float    g_agg[(size_t)MAXCID * N_REL * D];
__device__ float    g_logits[(size_t)NROWS * D];
__device__ int      g_ovf_cnt;
__device__ int4     g_ovf[OVF_CAP];

// ---------------- helpers ---------------------------------------------------
__device__ __forceinline__ u64 pack2(float lo, float hi) {
    u64 r; asm("mov.b64 %0, {%1, %2};" : "=l"(r) : "f"(lo), "f"(hi)); return r;
}
__device__ __forceinline__ void unpack2(u64 v, float& lo, float& hi) {
    asm("mov.b64 {%0, %1}, %2;" : "=f"(lo), "=f"(hi) : "l"(v));
}
__device__ __forceinline__ void fma2(u64& d, u64 a, u64 b) {
    asm("fma.rn.f32x2 %0, %1, %2, %0;" : "+l"(d) : "l"(a), "l"(b));
}

// ---------------- K0: clear table / bits / counters -------------------------
__global__ void clear_kernel() {
    int i = blockIdx.x * blockDim.x + threadIdx.x;
    if (i < N_NODES) g_table[i] = -1;
    if (i < NBITW) g_bits[i] = 0u;
    if (i < MAXCID * N_REL) g_counts[i] = 0;
    if (i == 0) { g_cnt = 0; g_ovf_cnt = 0; }
}

// ---------------- K1a: mark needed nodes ------------------------------------
__global__ void mark_kernel(const int* __restrict__ users, const int* __restrict__ items) {
    int r = blockIdx.x * blockDim.x + threadIdx.x;
    if (r >= NROWS) return;
    int node = (r < B_EVAL) ? users[r] : (N_USERS + items[r - B_EVAL]);
    g_table[node] = -2;               // idempotent
    atomicOr(&g_bits[node >> 5], 1u << (node & 31));
}

// ---------------- K1b: assign compact ids -----------------------------------
__global__ void assign_kernel() {
    int i = blockIdx.x * blockDim.x + threadIdx.x;
    if (i >= N_NODES) return;
    if (g_table[i] == -2) g_table[i] = atomicAdd(&g_cnt, 1);
}

// ---------------- K2: bin surviving edges (8-edge packs, bitmask filter) ----
__global__ void __launch_bounds__(256) bin_kernel(
    const int* __restrict__ rows, const int* __restrict__ cols,
    const float* __restrict__ vals)
{
    int i = blockIdx.x * blockDim.x + threadIdx.x;     // 8-edge pack index
    if (i >= TOTE / 8) return;
    int e0 = i * 8;
    int k  = e0 / NNZ;                                 // pack-uniform (NNZ%8==0)

    int4 ra = reinterpret_cast<const int4*>(rows)[2 * i];
    int4 rb = reinterpret_cast<const int4*>(rows)[2 * i + 1];
    int r[8] = {ra.x, ra.y, ra.z, ra.w, rb.x, rb.y, rb.z, rb.w};

    // 8 independent L1-resident bit tests
    bool h[8];
#pragma unroll
    for (int j = 0; j < 8; j++)
        h[j] = (g_bits[r[j] >> 5] >> (r[j] & 31)) & 1u;

    bool anyA = h[0] | h[1] | h[2] | h[3];
    bool anyB = h[4] | h[5] | h[6] | h[7];
    if (!(anyA | anyB)) return;

    int   c[8];
    float v[8];
    if (anyA) {
        int4   c4 = reinterpret_cast<const int4*>(cols)[2 * i];
        float4 v4 = reinterpret_cast<const float4*>(vals)[2 * i];
        c[0] = c4.x; c[1] = c4.y; c[2] = c4.z; c[3] = c4.w;
        v[0] = v4.x; v[1] = v4.y; v[2] = v4.z; v[3] = v4.w;
    }
    if (anyB) {
        int4   c4 = reinterpret_cast<const int4*>(cols)[2 * i + 1];
        float4 v4 = reinterpret_cast<const float4*>(vals)[2 * i + 1];
        c[4] = c4.x; c[5] = c4.y; c[6] = c4.z; c[7] = c4.w;
        v[4] = v4.x; v[5] = v4.y; v[6] = v4.z; v[7] = v4.w;
    }

    // independent table lookups for survivors only
    int cid[8];
#pragma unroll
    for (int j = 0; j < 8; j++) cid[j] = h[j] ? g_table[r[j]] : -1;

#pragma unroll
    for (int j = 0; j < 8; j++) {
        if (h[j]) {
            int b = cid[j] * N_REL + k;
            int pos = atomicAdd(&g_counts[b], 1);
            if (pos < CAP) {
                g_pairs[(size_t)b * CAP + pos] = make_float2(__int_as_float(c[j]), v[j]);
            } else {
                int oi = atomicAdd(&g_ovf_cnt, 1);
                if (oi < OVF_CAP) g_ovf[oi] = make_int4(cid[j], k, c[j], __float_as_int(v[j]));
            }
        }
    }
}

// ---------------- K3: warp-per-bucket gather (L1 broadcast loads, MLP=4) ----
__global__ void __launch_bounds__(256) gather_kernel(
    const float* __restrict__ uemb, const float* __restrict__ iemb)
{
    int gw   = (blockIdx.x * blockDim.x + threadIdx.x) >> 5;
    int lane = threadIdx.x & 31;
    if (gw >= MAXCID * N_REL) return;
    int cnt = g_counts[gw];
    if (cnt > CAP) cnt = CAP;
    float2 acc = make_float2(0.f, 0.f);
    const float2* pairs = &g_pairs[(size_t)gw * CAP];

    int t = 0;
    for (; t + 4 <= cnt; t += 4) {
        // warp-uniform broadcast loads (1 sector each, L1-resident bucket)
        float2 p0 = pairs[t + 0];
        float2 p1 = pairs[t + 1];
        float2 p2 = pairs[t + 2];
        float2 p3 = pairs[t + 3];
        int cc0 = __float_as_int(p0.x), cc1 = __float_as_int(p1.x);
        int cc2 = __float_as_int(p2.x), cc3 = __float_as_int(p3.x);
        const float2* e0 = (cc0 < N_USERS) ? reinterpret_cast<const float2*>(uemb + (size_t)cc0 * D)
                                           : reinterpret_cast<const float2*>(iemb + (size_t)(cc0 - N_USERS) * D);
        const float2* e1 = (cc1 < N_USERS) ? reinterpret_cast<const float2*>(uemb + (size_t)cc1 * D)
                                           : reinterpret_cast<const float2*>(iemb + (size_t)(cc1 - N_USERS) * D);
        const float2* e2 = (cc2 < N_USERS) ? reinterpret_cast<const float2*>(uemb + (size_t)cc2 * D)
                                           : reinterpret_cast<const float2*>(iemb + (size_t)(cc2 - N_USERS) * D);
        const float2* e3 = (cc3 < N_USERS) ? reinterpret_cast<const float2*>(uemb + (size_t)cc3 * D)
                                           : reinterpret_cast<const float2*>(iemb + (size_t)(cc3 - N_USERS) * D);
        float2 x0 = e0[lane];
        float2 x1 = e1[lane];
        float2 x2 = e2[lane];
        float2 x3 = e3[lane];
        acc.x += p0.y * x0.x; acc.y += p0.y * x0.y;
        acc.x += p1.y * x1.x; acc.y += p1.y * x1.y;
        acc.x += p2.y * x2.x; acc.y += p2.y * x2.y;
        acc.x += p3.y * x3.x; acc.y += p3.y * x3.y;
    }
    for (; t < cnt; t++) {
        float2 p = pairs[t];
        int cc = __float_as_int(p.x);
        const float2* er = (cc < N_USERS)
            ? reinterpret_cast<const float2*>(uemb + (size_t)cc * D)
            : reinterpret_cast<const float2*>(iemb + (size_t)(cc - N_USERS) * D);
        float2 x = er[lane];
        acc.x += p.y * x.x;
        acc.y += p.y * x.y;
    }
    reinterpret_cast<float2*>(g_agg + (size_t)gw * D)[lane] = acc;
}

// ---------------- K3b: overflow fallback (expected empty) -------------------
__global__ void ovf_kernel(const float* __restrict__ uemb, const float* __restrict__ iemb) {
    int i = blockIdx.x * blockDim.x + threadIdx.x;
    int n = g_ovf_cnt; if (n > OVF_CAP) n = OVF_CAP;
    if (i >= n) return;
    int4 e = g_ovf[i];
    int cid = e.x, k = e.y, c = e.z;
    float v = __int_as_float(e.w);
    const float* Erow = (c < N_USERS) ? (uemb + (size_t)c * D)
                                      : (iemb + (size_t)(c - N_USERS) * D);
    float* dst = g_agg + ((size_t)cid * N_REL + k) * D;
    for (int m = 0; m < 16; m++) {
        float4 x = reinterpret_cast<const float4*>(Erow)[m];
        asm volatile("red.global.add.v4.f32 [%0], {%1, %2, %3, %4};"
                     :: "l"(dst + m * 4), "f"(x.x * v), "f"(x.y * v),
                        "f"(x.z * v), "f"(x.w * v) : "memory");
    }
}

// ---------------- K4: fused dense chain (512 thr, 4x4 tiles, f32x2) ---------
__global__ void __launch_bounds__(512) gemm_kernel(
    const int* __restrict__ users, const int* __restrict__ items,
    const float* __restrict__ W_rel, const float* __restrict__ b_rel,
    const float* __restrict__ affine_W, const float* __restrict__ affine_b)
{
    __shared__ float sX[128 * 64];   // X tile, then Y tile
    __shared__ float sW[64 * 64];    // W_k, then A_k

    int t  = threadIdx.x;
    int tx = t & 15;        // col group: 4 cols
    int ty = t >> 4;        // row group: 4 rows (0..31)
    int rowBase = blockIdx.x * 128;

    u64 acc2[4][2];
#pragma unroll
    for (int i = 0; i < 4; i++) { acc2[i][0] = 0ull; acc2[i][1] = 0ull; }

    for (int k = 0; k < N_REL; k++) {
        __syncthreads();
        // load X tile: 4 threads per row, 4 float4 each
        {
            int r = t >> 2, q = t & 3;
            int brow = rowBase + r;
            int node = (brow < B_EVAL) ? users[brow] : (N_USERS + items[brow - B_EVAL]);
            int cid = g_table[node];
            const float4* src = reinterpret_cast<const float4*>(
                g_agg + ((size_t)cid * N_REL + k) * D) + q * 4;
            float4* dst = reinterpret_cast<float4*>(&sX[r * 64]) + q * 4;
#pragma unroll
            for (int m = 0; m < 4; m++) dst[m] = src[m];
        }
        // load W_k (1024 float4 / 512 threads)
        {
            const float4* src = reinterpret_cast<const float4*>(W_rel + (size_t)k * 64 * 64);
            float4* dst = reinterpret_cast<float4*>(sW);
            dst[t] = src[t];
            dst[t + 512] = src[t + 512];
        }
        __syncthreads();

        // GEMM1: acc1 = bias; acc1 += X @ W   (f32x2 packed)
        u64 acc1[4][2];
        {
            const u64* bp = reinterpret_cast<const u64*>(b_rel + (size_t)k * 64 + tx * 4);
            u64 b01 = bp[0], b23 = bp[1];
#pragma unroll
            for (int i = 0; i < 4; i++) { acc1[i][0] = b01; acc1[i][1] = b23; }
        }
        for (int kk = 0; kk < 64; kk++) {
            longlong2 bq = *reinterpret_cast<const longlong2*>(&sW[kk * 64 + tx * 4]);
            u64 b0 = (u64)bq.x, b1 = (u64)bq.y;
#pragma unroll
            for (int i = 0; i < 4; i++) {
                float a = sX[(ty * 4 + i) * 64 + kk];
                u64 a2 = pack2(a, a);
                fma2(acc1[i][0], a2, b0);
                fma2(acc1[i][1], a2, b1);
            }
        }
        __syncthreads();   // done reading sX / sW

        // leaky + write Y into sX; load A_k into sW
#pragma unroll
        for (int i = 0; i < 4; i++) {
            float y0, y1, y2, y3;
            unpack2(acc1[i][0], y0, y1);
            unpack2(acc1[i][1], y2, y3);
            y0 = (y0 > 0.f) ? y0 : 0.2f * y0;
            y1 = (y1 > 0.f) ? y1 : 0.2f * y1;
            y2 = (y2 > 0.f) ? y2 : 0.2f * y2;
            y3 = (y3 > 0.f) ? y3 : 0.2f * y3;
            *reinterpret_cast<float4*>(&sX[(ty * 4 + i) * 64 + tx * 4]) =
                make_float4(y0, y1, y2, y3);
        }
        {
            const float4* src = reinterpret_cast<const float4*>(affine_W + (size_t)k * 64 * 64);
            float4* dst = reinterpret_cast<float4*>(sW);
            dst[t] = src[t];
            dst[t + 512] = src[t + 512];
        }
        __syncthreads();

        // GEMM2: acc2 += Y @ A_k   (f32x2 packed)
        for (int kk = 0; kk < 64; kk++) {
            longlong2 bq = *reinterpret_cast<const longlong2*>(&sW[kk * 64 + tx * 4]);
            u64 b0 = (u64)bq.x, b1 = (u64)bq.y;
#pragma unroll
            for (int i = 0; i < 4; i++) {
                float a = sX[(ty * 4 + i) * 64 + kk];
                u64 a2 = pack2(a, a);
                fma2(acc2[i][0], a2, b0);
                fma2(acc2[i][1], a2, b1);
            }
        }
    }

    // epilogue: + affine_b, store logits
    float ab0 = affine_b[tx * 4 + 0], ab1 = affine_b[tx * 4 + 1];
    float ab2 = affine_b[tx * 4 + 2], ab3 = affine_b[tx * 4 + 3];
#pragma unroll
    for (int i = 0; i < 4; i++) {
        float v0, v1, v2, v3;
        unpack2(acc2[i][0], v0, v1);
        unpack2(acc2[i][1], v2, v3);
        int row = rowBase + ty * 4 + i;
        *reinterpret_cast<float4*>(&g_logits[(size_t)row * D + tx * 4]) =
            make_float4(v0 + ab0, v1 + ab1, v2 + ab2, v3 + ab3);
    }
}

// ---------------- K5: out[b] = dot(logits[b], logits[B+b]) ------------------
__global__ void dot_kernel(float* __restrict__ out) {
    int b = blockIdx.x * blockDim.x + threadIdx.x;
    if (b >= B_EVAL) return;
    const float4* u = reinterpret_cast<const float4*>(g_logits + (size_t)b * D);
    const float4* v = reinterpret_cast<const float4*>(g_logits + (size_t)(B_EVAL + b) * D);
    float s = 0.f;
#pragma unroll
    for (int m = 0; m < 16; m++) {
        float4 a = u[m], c = v[m];
        s += a.x * c.x + a.y * c.y + a.z * c.z + a.w * c.w;
    }
    out[b] = s;
}

// ---------------------------------------------------------------------------
extern "C" void kernel_launch(void* const* d_in, const int* in_sizes, int n_in,
                              void* d_out, int out_size) {
    const int*   users    = (const int*)  d_in[0];
    const int*   items    = (const int*)  d_in[1];
    const int*   rows     = (const int*)  d_in[2];
    const int*   cols     = (const int*)  d_in[3];
    const float* vals     = (const float*)d_in[4];
    const float* uemb     = (const float*)d_in[5];
    const float* iemb     = (const float*)d_in[6];
    const float* W_rel    = (const float*)d_in[7];
    const float* b_rel    = (const float*)d_in[8];
    const float* affine_W = (const float*)d_in[9];
    const float* affine_b = (const float*)d_in[10];
    float* out = (float*)d_out;

    clear_kernel<<<(MAXCID * N_REL + 255) / 256, 256>>>();
    mark_kernel<<<(NROWS + 255) / 256, 256>>>(users, items);
    assign_kernel<<<(N_NODES + 255) / 256, 256>>>();
    bin_kernel<<<(TOTE / 8 + 255) / 256, 256>>>(rows, cols, vals);
    gather_kernel<<<(MAXCID * N_REL) / 8, 256>>>(uemb, iemb);
    ovf_kernel<<<OVF_CAP / 256, 256>>>(uemb, iemb);
    gemm_kernel<<<NROWS / 128, 512>>>(users, items, W_rel, b_rel, affine_W, affine_b);
    dot_kernel<<<(B_EVAL + 255) / 256, 256>>>(out);
}

// round 12
// speedup vs baseline: 1.2261x; 1.1993x over previous
#include <cuda_runtime.h>
#include <cstdint>

#define N_USERS 100000
#define N_ITEMS 50000
#define N_NODES 150000
#define N_REL   5
#define NNZ     2000000
#define TOTE    (N_REL * NNZ)
#define D       64
#define B_EVAL  16384
#define NROWS   (2 * B_EVAL)
#define MAXCID  32768
#define CAP     64
#define OVF_CAP 8192
#define NBITW   ((N_NODES + 31) / 32)
#define NBUCK   (MAXCID * N_REL)

typedef unsigned long long u64;

// ---------------- device scratch (no allocations allowed) -------------------
__device__ int      g_table[N_NODES];                  // -1 unused / -2 marked / cid
__device__ unsigned g_bits[NBITW];                     // 18.75KB: L1-resident mask
__device__ int      g_cnt;
__device__ int      g_counts[NBUCK];
__device__ float2   g_pairs[(size_t)NBUCK * CAP];
__device__ float    g_agg[(size_t)NBUCK * D];
__device__ float    g_logits[(size_t)NROWS * D];
__device__ int      g_ovf_cnt;
__device__ int4     g_ovf[OVF_CAP];

// ---------------- helpers ---------------------------------------------------
__device__ __forceinline__ u64 pack2(float lo, float hi) {
    u64 r; asm("mov.b64 %0, {%1, %2};" : "=l"(r) : "f"(lo), "f"(hi)); return r;
}
__device__ __forceinline__ void unpack2(u64 v, float& lo, float& hi) {
    asm("mov.b64 {%0, %1}, %2;" : "=f"(lo), "=f"(hi) : "l"(v));
}
__device__ __forceinline__ void fma2(u64& d, u64 a, u64 b) {
    asm("fma.rn.f32x2 %0, %1, %2, %0;" : "+l"(d) : "l"(a), "l"(b));
}

// ---------------- K0: clear table / bits / counters -------------------------
__global__ void clear_kernel() {
    int i = blockIdx.x * blockDim.x + threadIdx.x;
    if (i < N_NODES) g_table[i] = -1;
    if (i < NBITW) g_bits[i] = 0u;
    if (i < NBUCK) g_counts[i] = 0;
    if (i == 0) { g_cnt = 0; g_ovf_cnt = 0; }
}

// ---------------- K1a: mark needed nodes ------------------------------------
__global__ void mark_kernel(const int* __restrict__ users, const int* __restrict__ items) {
    int r = blockIdx.x * blockDim.x + threadIdx.x;
    if (r >= NROWS) return;
    int node = (r < B_EVAL) ? users[r] : (N_USERS + items[r - B_EVAL]);
    g_table[node] = -2;               // idempotent
    atomicOr(&g_bits[node >> 5], 1u << (node & 31));
}

// ---------------- K1b: assign compact ids -----------------------------------
__global__ void assign_kernel() {
    int i = blockIdx.x * blockDim.x + threadIdx.x;
    if (i >= N_NODES) return;
    if (g_table[i] == -2) g_table[i] = atomicAdd(&g_cnt, 1);
}

// ---------------- K2: bin surviving edges (R9 4-wide bitmask — measured) ----
__global__ void __launch_bounds__(256) bin_kernel(
    const int* __restrict__ rows, const int* __restrict__ cols,
    const float* __restrict__ vals)
{
    int i = blockIdx.x * blockDim.x + threadIdx.x;     // pack index
    if (i >= TOTE / 4) return;
    int e0 = i * 4;
    int k  = e0 / NNZ;                                 // pack-uniform (NNZ%4==0)

    int4 r4 = reinterpret_cast<const int4*>(rows)[i];

    unsigned w0 = g_bits[r4.x >> 5];
    unsigned w1 = g_bits[r4.y >> 5];
    unsigned w2 = g_bits[r4.z >> 5];
    unsigned w3 = g_bits[r4.w >> 5];
    bool h[4];
    h[0] = (w0 >> (r4.x & 31)) & 1u;
    h[1] = (w1 >> (r4.y & 31)) & 1u;
    h[2] = (w2 >> (r4.z & 31)) & 1u;
    h[3] = (w3 >> (r4.w & 31)) & 1u;

    if (!(h[0] | h[1] | h[2] | h[3])) return;

    int4   c4 = reinterpret_cast<const int4*>(cols)[i];
    float4 v4 = reinterpret_cast<const float4*>(vals)[i];

    int r[4]   = {r4.x, r4.y, r4.z, r4.w};
    int c[4]   = {c4.x, c4.y, c4.z, c4.w};
    float v[4] = {v4.x, v4.y, v4.z, v4.w};

    int cid[4];
#pragma unroll
    for (int j = 0; j < 4; j++) cid[j] = h[j] ? g_table[r[j]] : -1;

#pragma unroll
    for (int j = 0; j < 4; j++) {
        if (h[j]) {
            int b = cid[j] * N_REL + k;
            int pos = atomicAdd(&g_counts[b], 1);
            if (pos < CAP) {
                g_pairs[(size_t)b * CAP + pos] = make_float2(__int_as_float(c[j]), v[j]);
            } else {
                int oi = atomicAdd(&g_ovf_cnt, 1);
                if (oi < OVF_CAP) g_ovf[oi] = make_int4(cid[j], k, c[j], __float_as_int(v[j]));
            }
        }
    }
}

// ---------------- K3: half-warp-per-bucket gather (2 buckets/warp, MLP=8) ---
__global__ void __launch_bounds__(256) gather_kernel(
    const float* __restrict__ uemb, const float* __restrict__ iemb)
{
    int ghw    = (blockIdx.x * blockDim.x + threadIdx.x) >> 4;   // bucket id
    int lane16 = threadIdx.x & 15;
    int halfs  = threadIdx.x & 16;                               // 0 or 16
    // grid covers NBUCK exactly (163840 / 16 per block): no partial warps
    int cnt = g_counts[ghw];
    if (cnt > CAP) cnt = CAP;
    int ocnt = __shfl_xor_sync(0xFFFFFFFFu, cnt, 16);            // sibling half's count
    int mx = cnt > ocnt ? cnt : ocnt;

    float4 acc = make_float4(0.f, 0.f, 0.f, 0.f);
    const float2* pairs = &g_pairs[(size_t)ghw * CAP];

    for (int base = 0; base < mx; base += 16) {
        // pad lanes carry (c=0, v=0): pad edges read row 0 (L1 hit) * 0
        float2 p = make_float2(0.f, 0.f);
        if (base + lane16 < cnt) p = pairs[base + lane16];
        int   c_l = __float_as_int(p.x);
        float v_l = p.y;
        int lim = mx - base; if (lim > 16) lim = 16;             // warp-uniform
        for (int t = 0; t < lim; t += 4) {
            int s = halfs + t;                                   // broadcast from own half
            int   cc0 = __shfl_sync(0xFFFFFFFFu, c_l, s + 0);
            int   cc1 = __shfl_sync(0xFFFFFFFFu, c_l, s + 1);
            int   cc2 = __shfl_sync(0xFFFFFFFFu, c_l, s + 2);
            int   cc3 = __shfl_sync(0xFFFFFFFFu, c_l, s + 3);
            float vv0 = __shfl_sync(0xFFFFFFFFu, v_l, s + 0);
            float vv1 = __shfl_sync(0xFFFFFFFFu, v_l, s + 1);
            float vv2 = __shfl_sync(0xFFFFFFFFu, v_l, s + 2);
            float vv3 = __shfl_sync(0xFFFFFFFFu, v_l, s + 3);
            const float4* e0 = (cc0 < N_USERS) ? reinterpret_cast<const float4*>(uemb + (size_t)cc0 * D)
                                               : reinterpret_cast<const float4*>(iemb + (size_t)(cc0 - N_USERS) * D);
            const float4* e1 = (cc1 < N_USERS) ? reinterpret_cast<const float4*>(uemb + (size_t)cc1 * D)
                                               : reinterpret_cast<const float4*>(iemb + (size_t)(cc1 - N_USERS) * D);
            const float4* e2 = (cc2 < N_USERS) ? reinterpret_cast<const float4*>(uemb + (size_t)cc2 * D)
                                               : reinterpret_cast<const float4*>(iemb + (size_t)(cc2 - N_USERS) * D);
            const float4* e3 = (cc3 < N_USERS) ? reinterpret_cast<const float4*>(uemb + (size_t)cc3 * D)
                                               : reinterpret_cast<const float4*>(iemb + (size_t)(cc3 - N_USERS) * D);
            float4 x0 = e0[lane16];
            float4 x1 = e1[lane16];
            float4 x2 = e2[lane16];
            float4 x3 = e3[lane16];
            acc.x += vv0 * x0.x; acc.y += vv0 * x0.y; acc.z += vv0 * x0.z; acc.w += vv0 * x0.w;
            acc.x += vv1 * x1.x; acc.y += vv1 * x1.y; acc.z += vv1 * x1.z; acc.w += vv1 * x1.w;
            acc.x += vv2 * x2.x; acc.y += vv2 * x2.y; acc.z += vv2 * x2.z; acc.w += vv2 * x2.w;
            acc.x += vv3 * x3.x; acc.y += vv3 * x3.y; acc.z += vv3 * x3.z; acc.w += vv3 * x3.w;
        }
    }
    reinterpret_cast<float4*>(g_agg + (size_t)ghw * D)[lane16] = acc;
}

// ---------------- K3b: overflow fallback (expected empty) -------------------
__global__ void ovf_kernel(const float* __restrict__ uemb, const float* __restrict__ iemb) {
    int i = blockIdx.x * blockDim.x + threadIdx.x;
    int n = g_ovf_cnt; if (n > OVF_CAP) n = OVF_CAP;
    if (i >= n) return;
    int4 e = g_ovf[i];
    int cid = e.x, k = e.y, c = e.z;
    float v = __int_as_float(e.w);
    const float* Erow = (c < N_USERS) ? (uemb + (size_t)c * D)
                                      : (iemb + (size_t)(c - N_USERS) * D);
    float* dst = g_agg + ((size_t)cid * N_REL + k) * D;
    for (int m = 0; m < 16; m++) {
        float4 x = reinterpret_cast<const float4*>(Erow)[m];
        asm volatile("red.global.add.v4.f32 [%0], {%1, %2, %3, %4};"
                     :: "l"(dst + m * 4), "f"(x.x * v), "f"(x.y * v),
                        "f"(x.z * v), "f"(x.w * v) : "memory");
    }
}

// ---------------- K4: fused dense chain (512 thr, 4x4 tiles, f32x2) ---------
__global__ void __launch_bounds__(512) gemm_kernel(
    const int* __restrict__ users, const int* __restrict__ items,
    const float* __restrict__ W_rel, const float* __restrict__ b_rel,
    const float* __restrict__ affine_W, const float* __restrict__ affine_b)
{
    __shared__ float sX[128 * 64];   // X tile, then Y tile
    __shared__ float sW[64 * 64];    // W_k, then A_k

    int t  = threadIdx.x;
    int tx = t & 15;        // col group: 4 cols
    int ty = t >> 4;        // row group: 4 rows (0..31)
    int rowBase = blockIdx.x * 128;

    u64 acc2[4][2];
#pragma unroll
    for (int i = 0; i < 4; i++) { acc2[i][0] = 0ull; acc2[i][1] = 0ull; }

    for (int k = 0; k < N_REL; k++) {
        __syncthreads();
        // load X tile: 4 threads per row, 4 float4 each
        {
            int r = t >> 2, q = t & 3;
            int brow = rowBase + r;
            int node = (brow < B_EVAL) ? users[brow] : (N_USERS + items[brow - B_EVAL]);
            int cid = g_table[node];
            const float4* src = reinterpret_cast<const float4*>(
                g_agg + ((size_t)cid * N_REL + k) * D) + q * 4;
            float4* dst = reinterpret_cast<float4*>(&sX[r * 64]) + q * 4;
#pragma unroll
            for (int m = 0; m < 4; m++) dst[m] = src[m];
        }
        // load W_k (1024 float4 / 512 threads)
        {
            const float4* src = reinterpret_cast<const float4*>(W_rel + (size_t)k * 64 * 64);
            float4* dst = reinterpret_cast<float4*>(sW);
            dst[t] = src[t];
            dst[t + 512] = src[t + 512];
        }
        __syncthreads();

        // GEMM1: acc1 = bias; acc1 += X @ W   (f32x2 packed)
        u64 acc1[4][2];
        {
            const u64* bp = reinterpret_cast<const u64*>(b_rel + (size_t)k * 64 + tx * 4);
            u64 b01 = bp[0], b23 = bp[1];
#pragma unroll
            for (int i = 0; i < 4; i++) { acc1[i][0] = b01; acc1[i][1] = b23; }
        }
        for (int kk = 0; kk < 64; kk++) {
            longlong2 bq = *reinterpret_cast<const longlong2*>(&sW[kk * 64 + tx * 4]);
            u64 b0 = (u64)bq.x, b1 = (u64)bq.y;
#pragma unroll
            for (int i = 0; i < 4; i++) {
                float a = sX[(ty * 4 + i) * 64 + kk];
                u64 a2 = pack2(a, a);
                fma2(acc1[i][0], a2, b0);
                fma2(acc1[i][1], a2, b1);
            }
        }
        __syncthreads();   // done reading sX / sW

        // leaky + write Y into sX; load A_k into sW
#pragma unroll
        for (int i = 0; i < 4; i++) {
            float y0, y1, y2, y3;
            unpack2(acc1[i][0], y0, y1);
            unpack2(acc1[i][1], y2, y3);
            y0 = (y0 > 0.f) ? y0 : 0.2f * y0;
            y1 = (y1 > 0.f) ? y1 : 0.2f * y1;
            y2 = (y2 > 0.f) ? y2 : 0.2f * y2;
            y3 = (y3 > 0.f) ? y3 : 0.2f * y3;
            *reinterpret_cast<float4*>(&sX[(ty * 4 + i) * 64 + tx * 4]) =
                make_float4(y0, y1, y2, y3);
        }
        {
            const float4* src = reinterpret_cast<const float4*>(affine_W + (size_t)k * 64 * 64);
            float4* dst = reinterpret_cast<float4*>(sW);
            dst[t] = src[t];
            dst[t + 512] = src[t + 512];
        }
        __syncthreads();

        // GEMM2: acc2 += Y @ A_k   (f32x2 packed)
        for (int kk = 0; kk < 64; kk++) {
            longlong2 bq = *reinterpret_cast<const longlong2*>(&sW[kk * 64 + tx * 4]);
            u64 b0 = (u64)bq.x, b1 = (u64)bq.y;
#pragma unroll
            for (int i = 0; i < 4; i++) {
                float a = sX[(ty * 4 + i) * 64 + kk];
                u64 a2 = pack2(a, a);
                fma2(acc2[i][0], a2, b0);
                fma2(acc2[i][1], a2, b1);
            }
        }
    }

    // epilogue: + affine_b, store logits
    float ab0 = affine_b[tx * 4 + 0], ab1 = affine_b[tx * 4 + 1];
    float ab2 = affine_b[tx * 4 + 2], ab3 = affine_b[tx * 4 + 3];
#pragma unroll
    for (int i = 0; i < 4; i++) {
        float v0, v1, v2, v3;
        unpack2(acc2[i][0], v0, v1);
        unpack2(acc2[i][1], v2, v3);
        int row = rowBase + ty * 4 + i;
        *reinterpret_cast<float4*>(&g_logits[(size_t)row * D + tx * 4]) =
            make_float4(v0 + ab0, v1 + ab1, v2 + ab2, v3 + ab3);
    }
}

// ---------------- K5: out[b] = dot(logits[b], logits[B+b]) ------------------
__global__ void dot_kernel(float* __restrict__ out) {
    int b = blockIdx.x * blockDim.x + threadIdx.x;
    if (b >= B_EVAL) return;
    const float4* u = reinterpret_cast<const float4*>(g_logits + (size_t)b * D);
    const float4* v = reinterpret_cast<const float4*>(g_logits + (size_t)(B_EVAL + b) * D);
    float s = 0.f;
#pragma unroll
    for (int m = 0; m < 16; m++) {
        float4 a = u[m], c = v[m];
        s += a.x * c.x + a.y * c.y + a.z * c.z + a.w * c.w;
    }
    out[b] = s;
}

// ---------------------------------------------------------------------------
extern "C" void kernel_launch(void* const* d_in, const int* in_sizes, int n_in,
                              void* d_out, int out_size) {
    const int*   users    = (const int*)  d_in[0];
    const int*   items    = (const int*)  d_in[1];
    const int*   rows     = (const int*)  d_in[2];
    const int*   cols     = (const int*)  d_in[3];
    const float* vals     = (const float*)d_in[4];
    const float* uemb     = (const float*)d_in[5];
    const float* iemb     = (const float*)d_in[6];
    const float* W_rel    = (const float*)d_in[7];
    const float* b_rel    = (const float*)d_in[8];
    const float* affine_W = (const float*)d_in[9];
    const float* affine_b = (const float*)d_in[10];
    float* out = (float*)d_out;

    clear_kernel<<<(NBUCK + 255) / 256, 256>>>();
    mark_kernel<<<(NROWS + 255) / 256, 256>>>(users, items);
    assign_kernel<<<(N_NODES + 255) / 256, 256>>>();
    bin_kernel<<<(TOTE / 4 + 255) / 256, 256>>>(rows, cols, vals);
    gather_kernel<<<NBUCK / 16, 256>>>(uemb, iemb);
    ovf_kernel<<<OVF_CAP / 256, 256>>>(uemb, iemb);
    gemm_kernel<<<NROWS / 128, 512>>>(users, items, W_rel, b_rel, affine_W, affine_b);
    dot_kernel<<<(B_EVAL + 255) / 256, 256>>>(out);
}

// round 13
// speedup vs baseline: 1.2672x; 1.0335x over previous
#include <cuda_runtime.h>
#include <cstdint>

#define N_USERS 100000
#define N_ITEMS 50000
#define N_NODES 150000
#define N_REL   5
#define NNZ     2000000
#define TOTE    (N_REL * NNZ)
#define D       64
#define B_EVAL  16384
#define NROWS   (2 * B_EVAL)
#define MAXCID  32768
#define CAP     64
#define OVF_CAP 8192
#define NBITW   ((N_NODES + 31) / 32)
#define NBUCK   (MAXCID * N_REL)
#define XPITCH  68              // padded sX row stride (floats): kills a-load bank conflicts

typedef unsigned long long u64;

// ---------------- device scratch (no allocations allowed) -------------------
__device__ int      g_table[N_NODES];                  // -1 unused / -2 marked / cid
__device__ unsigned g_bits[NBITW];                     // 18.75KB: L1-resident mask
__device__ int      g_cnt;
__device__ int      g_counts[NBUCK];
__device__ float2   g_pairs[(size_t)NBUCK * CAP];
__device__ float    g_agg[(size_t)NBUCK * D];
__device__ float    g_logits[(size_t)NROWS * D];
__device__ int      g_ovf_cnt;
__device__ int4     g_ovf[OVF_CAP];

// ---------------- helpers ---------------------------------------------------
__device__ __forceinline__ u64 pack2(float lo, float hi) {
    u64 r; asm("mov.b64 %0, {%1, %2};" : "=l"(r) : "f"(lo), "f"(hi)); return r;
}
__device__ __forceinline__ void unpack2(u64 v, float& lo, float& hi) {
    asm("mov.b64 {%0, %1}, %2;" : "=f"(lo), "=f"(hi) : "l"(v));
}
__device__ __forceinline__ void fma2(u64& d, u64 a, u64 b) {
    asm("fma.rn.f32x2 %0, %1, %2, %0;" : "+l"(d) : "l"(a), "l"(b));
}
__device__ __forceinline__ float f4c(const float4& f, int q) {
    return q == 0 ? f.x : q == 1 ? f.y : q == 2 ? f.z : f.w;
}

// ---------------- K0: clear table / bits / counters -------------------------
__global__ void clear_kernel() {
    int i = blockIdx.x * blockDim.x + threadIdx.x;
    if (i < N_NODES) g_table[i] = -1;
    if (i < NBITW) g_bits[i] = 0u;
    if (i < NBUCK) g_counts[i] = 0;
    if (i == 0) { g_cnt = 0; g_ovf_cnt = 0; }
}

// ---------------- K1a: mark needed nodes ------------------------------------
__global__ void mark_kernel(const int* __restrict__ users, const int* __restrict__ items) {
    int r = blockIdx.x * blockDim.x + threadIdx.x;
    if (r >= NROWS) return;
    int node = (r < B_EVAL) ? users[r] : (N_USERS + items[r - B_EVAL]);
    g_table[node] = -2;               // idempotent
    atomicOr(&g_bits[node >> 5], 1u << (node & 31));
}

// ---------------- K1b: assign compact ids -----------------------------------
__global__ void assign_kernel() {
    int i = blockIdx.x * blockDim.x + threadIdx.x;
    if (i >= N_NODES) return;
    if (g_table[i] == -2) g_table[i] = atomicAdd(&g_cnt, 1);
}

// ---------------- K2: bin surviving edges (4-wide bitmask — measured best) --
__global__ void __launch_bounds__(256) bin_kernel(
    const int* __restrict__ rows, const int* __restrict__ cols,
    const float* __restrict__ vals)
{
    int i = blockIdx.x * blockDim.x + threadIdx.x;     // pack index
    if (i >= TOTE / 4) return;
    int e0 = i * 4;
    int k  = e0 / NNZ;                                 // pack-uniform (NNZ%4==0)

    int4 r4 = reinterpret_cast<const int4*>(rows)[i];

    unsigned w0 = g_bits[r4.x >> 5];
    unsigned w1 = g_bits[r4.y >> 5];
    unsigned w2 = g_bits[r4.z >> 5];
    unsigned w3 = g_bits[r4.w >> 5];
    bool h[4];
    h[0] = (w0 >> (r4.x & 31)) & 1u;
    h[1] = (w1 >> (r4.y & 31)) & 1u;
    h[2] = (w2 >> (r4.z & 31)) & 1u;
    h[3] = (w3 >> (r4.w & 31)) & 1u;

    if (!(h[0] | h[1] | h[2] | h[3])) return;

    int4   c4 = reinterpret_cast<const int4*>(cols)[i];
    float4 v4 = reinterpret_cast<const float4*>(vals)[i];

    int r[4]   = {r4.x, r4.y, r4.z, r4.w};
    int c[4]   = {c4.x, c4.y, c4.z, c4.w};
    float v[4] = {v4.x, v4.y, v4.z, v4.w};

    int cid[4];
#pragma unroll
    for (int j = 0; j < 4; j++) cid[j] = h[j] ? g_table[r[j]] : -1;

#pragma unroll
    for (int j = 0; j < 4; j++) {
        if (h[j]) {
            int b = cid[j] * N_REL + k;
            int pos = atomicAdd(&g_counts[b], 1);
            if (pos < CAP) {
                g_pairs[(size_t)b * CAP + pos] = make_float2(__int_as_float(c[j]), v[j]);
            } else {
                int oi = atomicAdd(&g_ovf_cnt, 1);
                if (oi < OVF_CAP) g_ovf[oi] = make_int4(cid[j], k, c[j], __float_as_int(v[j]));
            }
        }
    }
}

// ---------------- K3: half-warp-per-bucket gather (measured best) -----------
__global__ void __launch_bounds__(256) gather_kernel(
    const float* __restrict__ uemb, const float* __restrict__ iemb)
{
    int ghw    = (blockIdx.x * blockDim.x + threadIdx.x) >> 4;   // bucket id
    int lane16 = threadIdx.x & 15;
    int halfs  = threadIdx.x & 16;                               // 0 or 16
    int cnt = g_counts[ghw];
    if (cnt > CAP) cnt = CAP;
    int ocnt = __shfl_xor_sync(0xFFFFFFFFu, cnt, 16);            // sibling half's count
    int mx = cnt > ocnt ? cnt : ocnt;

    float4 acc = make_float4(0.f, 0.f, 0.f, 0.f);
    const float2* pairs = &g_pairs[(size_t)ghw * CAP];

    for (int base = 0; base < mx; base += 16) {
        float2 p = make_float2(0.f, 0.f);
        if (base + lane16 < cnt) p = pairs[base + lane16];
        int   c_l = __float_as_int(p.x);
        float v_l = p.y;
        int lim = mx - base; if (lim > 16) lim = 16;             // warp-uniform
        for (int t = 0; t < lim; t += 4) {
            int s = halfs + t;                                   // broadcast from own half
            int   cc0 = __shfl_sync(0xFFFFFFFFu, c_l, s + 0);
            int   cc1 = __shfl_sync(0xFFFFFFFFu, c_l, s + 1);
            int   cc2 = __shfl_sync(0xFFFFFFFFu, c_l, s + 2);
            int   cc3 = __shfl_sync(0xFFFFFFFFu, c_l, s + 3);
            float vv0 = __shfl_sync(0xFFFFFFFFu, v_l, s + 0);
            float vv1 = __shfl_sync(0xFFFFFFFFu, v_l, s + 1);
            float vv2 = __shfl_sync(0xFFFFFFFFu, v_l, s + 2);
            float vv3 = __shfl_sync(0xFFFFFFFFu, v_l, s + 3);
            const float4* e0 = (cc0 < N_USERS) ? reinterpret_cast<const float4*>(uemb + (size_t)cc0 * D)
                                               : reinterpret_cast<const float4*>(iemb + (size_t)(cc0 - N_USERS) * D);
            const float4* e1 = (cc1 < N_USERS) ? reinterpret_cast<const float4*>(uemb + (size_t)cc1 * D)
                                               : reinterpret_cast<const float4*>(iemb + (size_t)(cc1 - N_USERS) * D);
            const float4* e2 = (cc2 < N_USERS) ? reinterpret_cast<const float4*>(uemb + (size_t)cc2 * D)
                                               : reinterpret_cast<const float4*>(iemb + (size_t)(cc2 - N_USERS) * D);
            const float4* e3 = (cc3 < N_USERS) ? reinterpret_cast<const float4*>(uemb + (size_t)cc3 * D)
                                               : reinterpret_cast<const float4*>(iemb + (size_t)(cc3 - N_USERS) * D);
            float4 x0 = e0[lane16];
            float4 x1 = e1[lane16];
            float4 x2 = e2[lane16];
            float4 x3 = e3[lane16];
            acc.x += vv0 * x0.x; acc.y += vv0 * x0.y; acc.z += vv0 * x0.z; acc.w += vv0 * x0.w;
            acc.x += vv1 * x1.x; acc.y += vv1 * x1.y; acc.z += vv1 * x1.z; acc.w += vv1 * x1.w;
            acc.x += vv2 * x2.x; acc.y += vv2 * x2.y; acc.z += vv2 * x2.z; acc.w += vv2 * x2.w;
            acc.x += vv3 * x3.x; acc.y += vv3 * x3.y; acc.z += vv3 * x3.z; acc.w += vv3 * x3.w;
        }
    }
    reinterpret_cast<float4*>(g_agg + (size_t)ghw * D)[lane16] = acc;
}

// ---------------- K3b: overflow fallback (expected empty) -------------------
__global__ void ovf_kernel(const float* __restrict__ uemb, const float* __restrict__ iemb) {
    int i = blockIdx.x * blockDim.x + threadIdx.x;
    int n = g_ovf_cnt; if (n > OVF_CAP) n = OVF_CAP;
    if (i >= n) return;
    int4 e = g_ovf[i];
    int cid = e.x, k = e.y, c = e.z;
    float v = __int_as_float(e.w);
    const float* Erow = (c < N_USERS) ? (uemb + (size_t)c * D)
                                      : (iemb + (size_t)(c - N_USERS) * D);
    float* dst = g_agg + ((size_t)cid * N_REL + k) * D;
    for (int m = 0; m < 16; m++) {
        float4 x = reinterpret_cast<const float4*>(Erow)[m];
        asm volatile("red.global.add.v4.f32 [%0], {%1, %2, %3, %4};"
                     :: "l"(dst + m * 4), "f"(x.x * v), "f"(x.y * v),
                        "f"(x.z * v), "f"(x.w * v) : "memory");
    }
}

// ---------------- K4: fused dense chain (padded sX, float4 a-loads) ---------
__global__ void __launch_bounds__(512) gemm_kernel(
    const int* __restrict__ users, const int* __restrict__ items,
    const float* __restrict__ W_rel, const float* __restrict__ b_rel,
    const float* __restrict__ affine_W, const float* __restrict__ affine_b)
{
    __shared__ float sX[128 * XPITCH];   // X tile, then Y tile (padded rows)
    __shared__ float sW[64 * 64];        // W_k, then A_k

    int t  = threadIdx.x;
    int tx = t & 15;        // col group: 4 cols
    int ty = t >> 4;        // row group: 4 rows (0..31)
    int rowBase = blockIdx.x * 128;

    u64 acc2[4][2];
#pragma unroll
    for (int i = 0; i < 4; i++) { acc2[i][0] = 0ull; acc2[i][1] = 0ull; }

    for (int k = 0; k < N_REL; k++) {
        __syncthreads();
        // load X tile: 4 threads per row, 4 float4 each
        {
            int r = t >> 2, q = t & 3;
            int brow = rowBase + r;
            int node = (brow < B_EVAL) ? users[brow] : (N_USERS + items[brow - B_EVAL]);
            int cid = g_table[node];
            const float4* src = reinterpret_cast<const float4*>(
                g_agg + ((size_t)cid * N_REL + k) * D) + q * 4;
            float4* dst = reinterpret_cast<float4*>(&sX[r * XPITCH]) + q * 4;
#pragma unroll
            for (int m = 0; m < 4; m++) dst[m] = src[m];
        }
        // load W_k (1024 float4 / 512 threads)
        {
            const float4* src = reinterpret_cast<const float4*>(W_rel + (size_t)k * 64 * 64);
            float4* dst = reinterpret_cast<float4*>(sW);
            dst[t] = src[t];
            dst[t + 512] = src[t + 512];
        }
        __syncthreads();

        // GEMM1: acc1 = bias; acc1 += X @ W   (4-kk groups, float4 a-loads)
        u64 acc1[4][2];
        {
            const u64* bp = reinterpret_cast<const u64*>(b_rel + (size_t)k * 64 + tx * 4);
            u64 b01 = bp[0], b23 = bp[1];
#pragma unroll
            for (int i = 0; i < 4; i++) { acc1[i][0] = b01; acc1[i][1] = b23; }
        }
        for (int kk = 0; kk < 64; kk += 4) {
            float4 a4[4];
#pragma unroll
            for (int i = 0; i < 4; i++)
                a4[i] = *reinterpret_cast<const float4*>(&sX[(ty * 4 + i) * XPITCH + kk]);
#pragma unroll
            for (int q = 0; q < 4; q++) {
                longlong2 bq = *reinterpret_cast<const longlong2*>(&sW[(kk + q) * 64 + tx * 4]);
                u64 b0 = (u64)bq.x, b1 = (u64)bq.y;
#pragma unroll
                for (int i = 0; i < 4; i++) {
                    float a = f4c(a4[i], q);
                    u64 a2 = pack2(a, a);
                    fma2(acc1[i][0], a2, b0);
                    fma2(acc1[i][1], a2, b1);
                }
            }
        }
        __syncthreads();   // done reading sX / sW

        // leaky + write Y into sX; load A_k into sW
#pragma unroll
        for (int i = 0; i < 4; i++) {
            float y0, y1, y2, y3;
            unpack2(acc1[i][0], y0, y1);
            unpack2(acc1[i][1], y2, y3);
            y0 = (y0 > 0.f) ? y0 : 0.2f * y0;
            y1 = (y1 > 0.f) ? y1 : 0.2f * y1;
            y2 = (y2 > 0.f) ? y2 : 0.2f * y2;
            y3 = (y3 > 0.f) ? y3 : 0.2f * y3;
            *reinterpret_cast<float4*>(&sX[(ty * 4 + i) * XPITCH + tx * 4]) =
                make_float4(y0, y1, y2, y3);
        }
        {
            const float4* src = reinterpret_cast<const float4*>(affine_W + (size_t)k * 64 * 64);
            float4* dst = reinterpret_cast<float4*>(sW);
            dst[t] = src[t];
            dst[t + 512] = src[t + 512];
        }
        __syncthreads();

        // GEMM2: acc2 += Y @ A_k   (4-kk groups, float4 a-loads)
        for (int kk = 0; kk < 64; kk += 4) {
            float4 a4[4];
#pragma unroll
            for (int i = 0; i < 4; i++)
                a4[i] = *reinterpret_cast<const float4*>(&sX[(ty * 4 + i) * XPITCH + kk]);
#pragma unroll
            for (int q = 0; q < 4; q++) {
                longlong2 bq = *reinterpret_cast<const longlong2*>(&sW[(kk + q) * 64 + tx * 4]);
                u64 b0 = (u64)bq.x, b1 = (u64)bq.y;
#pragma unroll
                for (int i = 0; i < 4; i++) {
                    float a = f4c(a4[i], q);
                    u64 a2 = pack2(a, a);
                    fma2(acc2[i][0], a2, b0);
                    fma2(acc2[i][1], a2, b1);
                }
            }
        }
    }

    // epilogue: + affine_b, store logits
    float ab0 = affine_b[tx * 4 + 0], ab1 = affine_b[tx * 4 + 1];
    float ab2 = affine_b[tx * 4 + 2], ab3 = affine_b[tx * 4 + 3];
#pragma unroll
    for (int i = 0; i < 4; i++) {
        float v0, v1, v2, v3;
        unpack2(acc2[i][0], v0, v1);
        unpack2(acc2[i][1], v2, v3);
        int row = rowBase + ty * 4 + i;
        *reinterpret_cast<float4*>(&g_logits[(size_t)row * D + tx * 4]) =
            make_float4(v0 + ab0, v1 + ab1, v2 + ab2, v3 + ab3);
    }
}

// ---------------- K5: out[b] = dot(logits[b], logits[B+b]) ------------------
__global__ void dot_kernel(float* __restrict__ out) {
    int b = blockIdx.x * blockDim.x + threadIdx.x;
    if (b >= B_EVAL) return;
    const float4* u = reinterpret_cast<const float4*>(g_logits + (size_t)b * D);
    const float4* v = reinterpret_cast<const float4*>(g_logits + (size_t)(B_EVAL + b) * D);
    float s = 0.f;
#pragma unroll
    for (int m = 0; m < 16; m++) {
        float4 a = u[m], c = v[m];
        s += a.x * c.x + a.y * c.y + a.z * c.z + a.w * c.w;
    }
    out[b] = s;
}

// ---------------------------------------------------------------------------
extern "C" void kernel_launch(void* const* d_in, const int* in_sizes, int n_in,
                              void* d_out, int out_size) {
    const int*   users    = (const int*)  d_in[0];
    const int*   items    = (const int*)  d_in[1];
    const int*   rows     = (const int*)  d_in[2];
    const int*   cols     = (const int*)  d_in[3];
    const float* vals     = (const float*)d_in[4];
    const float* uemb     = (const float*)d_in[5];
    const float* iemb     = (const float*)d_in[6];
    const float* W_rel    = (const float*)d_in[7];
    const float* b_rel    = (const float*)d_in[8];
    const float* affine_W = (const float*)d_in[9];
    const float* affine_b = (const float*)d_in[10];
    float* out = (float*)d_out;

    clear_kernel<<<(NBUCK + 255) / 256, 256>>>();
    mark_kernel<<<(NROWS + 255) / 256, 256>>>(users, items);
    assign_kernel<<<(N_NODES + 255) / 256, 256>>>();
    bin_kernel<<<(TOTE / 4 + 255) / 256, 256>>>(rows, cols, vals);
    gather_kernel<<<NBUCK / 16, 256>>>(uemb, iemb);
    ovf_kernel<<<OVF_CAP / 256, 256>>>(uemb, iemb);
    gemm_kernel<<<NROWS / 128, 512>>>(users, items, W_rel, b_rel, affine_W, affine_b);
    dot_kernel<<<(B_EVAL + 255) / 256, 256>>>(out);
}